// round 9
// baseline (speedup 1.0000x reference)
#include <cuda_runtime.h>
#include <cuda_bf16.h>
#include <cstdint>

// ContrastiveLoss: loss = -log(num/(den+1e-9)+1e-10)
//   S[i,j] = exp((x[i] . y_sel[j]) / 0.3),  y_sel = y.reshape(4096,128)
//   pos(i,j) = (track_idxs[i] == (j % 512))
// x [32768,128] f32, track_idxs [32768] i32, y [512,8,128] f32, out [1] f32.
//
// bf16 mma.sync.m16n8k16; CTA tile 128x64 (warp tile 32x32, 8 warps),
// 3 CTAs/SM (24 warps) for latency hiding, fused packed-f32x2 exp + masked
// reduce, last-CTA finalize.

#define NROWS 32768
#define NCOLS 4096
#define NTILE_R (NROWS / 128)   /* 256 */
#define NTILE_C (NCOLS / 64)    /* 64  */
#define NPART (NTILE_R * NTILE_C) /* 16384 */

__device__ __nv_bfloat16 g_xb[NROWS * 128];
__device__ __nv_bfloat16 g_yb[NCOLS * 128];
__device__ float2 g_partials[NPART];
__device__ int g_ctr = 0;

// ---------------- helpers ----------------
__device__ __forceinline__ uint32_t smem_to_u32(const void* p) {
    uint32_t a;
    asm("{ .reg .u64 t; cvta.to.shared.u64 t, %1; cvt.u32.u64 %0, t; }"
        : "=r"(a) : "l"(p));
    return a;
}

__device__ __forceinline__ void cp_async16(uint32_t saddr, const void* gaddr) {
    asm volatile("cp.async.cg.shared.global [%0], [%1], 16;"
                 :: "r"(saddr), "l"(gaddr) : "memory");
}
__device__ __forceinline__ void cp_async_wait_all() {
    asm volatile("cp.async.commit_group;\n\tcp.async.wait_group 0;" ::: "memory");
}

__device__ __forceinline__ void ldsm_x4(uint32_t& r0, uint32_t& r1, uint32_t& r2,
                                        uint32_t& r3, uint32_t addr) {
    asm volatile("ldmatrix.sync.aligned.m8n8.x4.shared.b16 {%0,%1,%2,%3}, [%4];"
                 : "=r"(r0), "=r"(r1), "=r"(r2), "=r"(r3) : "r"(addr));
}

__device__ __forceinline__ void mma16816(float& d0, float& d1, float& d2, float& d3,
                                         uint32_t a0, uint32_t a1, uint32_t a2,
                                         uint32_t a3, uint32_t b0, uint32_t b1) {
    asm volatile(
        "mma.sync.aligned.m16n8k16.row.col.f32.bf16.bf16.f32 "
        "{%0,%1,%2,%3}, {%4,%5,%6,%7}, {%8,%9}, {%0,%1,%2,%3};"
        : "+f"(d0), "+f"(d1), "+f"(d2), "+f"(d3)
        : "r"(a0), "r"(a1), "r"(a2), "r"(a3), "r"(b0), "r"(b1));
}

// packed f32x2 ops
__device__ __forceinline__ unsigned long long pk2(float lo, float hi) {
    unsigned long long r;
    asm("mov.b64 %0, {%1, %2};" : "=l"(r) : "f"(lo), "f"(hi));
    return r;
}
__device__ __forceinline__ void upk2(unsigned long long v, float& lo, float& hi) {
    asm("mov.b64 {%0, %1}, %2;" : "=f"(lo), "=f"(hi) : "l"(v));
}
__device__ __forceinline__ void upk2u(unsigned long long v, uint32_t& lo, uint32_t& hi) {
    asm("mov.b64 {%0, %1}, %2;" : "=r"(lo), "=r"(hi) : "l"(v));
}
__device__ __forceinline__ unsigned long long pk2u(uint32_t lo, uint32_t hi) {
    unsigned long long r;
    asm("mov.b64 %0, {%1, %2};" : "=l"(r) : "r"(lo), "r"(hi));
    return r;
}
__device__ __forceinline__ unsigned long long addx2(unsigned long long a, unsigned long long b) {
    unsigned long long d;
    asm("add.rn.f32x2 %0, %1, %2;" : "=l"(d) : "l"(a), "l"(b));
    return d;
}
__device__ __forceinline__ unsigned long long mulx2(unsigned long long a, unsigned long long b) {
    unsigned long long d;
    asm("mul.rn.f32x2 %0, %1, %2;" : "=l"(d) : "l"(a), "l"(b));
    return d;
}
__device__ __forceinline__ unsigned long long fmax2(unsigned long long a, unsigned long long b,
                                                    unsigned long long c) {
    unsigned long long d;
    asm("fma.rn.f32x2 %0, %1, %2, %3;" : "=l"(d) : "l"(a), "l"(b), "l"(c));
    return d;
}

// blocked-atom K-major SW128 layouts.
// A tile: 128 rows x 128 bf16 -> 16 atom-rows x 2 atom-cols (32KB).
__device__ __forceinline__ uint32_t tile_off_a(int row, int col8) {
    uint32_t atom = (uint32_t)((row >> 3) + ((col8 >> 6) << 4));
    uint32_t boff = atom * 1024u + (uint32_t)(row & 7) * 128u + (uint32_t)(col8 & 63) * 2u;
    return boff ^ ((boff >> 3) & 0x70u);
}
// B tile: 64 rows x 128 bf16 -> 8 atom-rows x 2 atom-cols (16KB).
__device__ __forceinline__ uint32_t tile_off_b(int row, int col8) {
    uint32_t atom = (uint32_t)((row >> 3) + ((col8 >> 6) << 3));
    uint32_t boff = atom * 1024u + (uint32_t)(row & 7) * 128u + (uint32_t)(col8 & 63) * 2u;
    return boff ^ ((boff >> 3) & 0x70u);
}

#define OFF_TRK  0       /* 128 ints */
#define OFF_RED  512     /* 16 floats */
#define OFF_DRED 576     /* 16 doubles */
#define OFF_FLAG 704     /* int */
#define OFF_A    1024    /* 32KB */
#define OFF_B    33792   /* 16KB */
#define SMEM_TOTAL 50176

// ---------------- kernels ----------------
__global__ __launch_bounds__(256)
void cvt_bf16_all(const float* __restrict__ x, const float* __restrict__ y) {
    const int xn4 = NROWS * 128 / 4;
    const int yn4 = NCOLS * 128 / 4;
    int i = blockIdx.x * blockDim.x + threadIdx.x;
    const float4* src;
    uint2* dst;
    int idx;
    if (i < xn4) {
        src = (const float4*)x; dst = (uint2*)g_xb; idx = i;
    } else if (i < xn4 + yn4) {
        src = (const float4*)y; dst = (uint2*)g_yb; idx = i - xn4;
    } else return;
    float4 v = src[idx];
    __nv_bfloat162 a = __floats2bfloat162_rn(v.x, v.y);
    __nv_bfloat162 b = __floats2bfloat162_rn(v.z, v.w);
    uint2 o;
    o.x = *(uint32_t*)&a;
    o.y = *(uint32_t*)&b;
    dst[idx] = o;
}

__global__ __launch_bounds__(256, 3)
void cl_mma_kernel(const int* __restrict__ trk, float* __restrict__ out) {
    extern __shared__ char smem[];
    const uint32_t sb = smem_to_u32(smem);
    const int tid = threadIdx.x;
    const int wid = tid >> 5, lane = tid & 31;
    const int bx = blockIdx.x;   // col tile 0..63 (64 cols each)
    const int by = blockIdx.y;   // row tile 0..255

    const int wrow = wid & 3;    // 4 row groups x 32 rows
    const int wcol = wid >> 2;   // 2 col groups x 32 cols

    if (tid < 128) ((int*)(smem + OFF_TRK))[tid] = trk[by * 128 + tid];

    // Stage A (128x128 bf16 = 2048 x 16B) and B (64x128 bf16 = 1024 x 16B).
    {
        const char* xg = (const char*)g_xb + (size_t)by * 32768;
        const char* yg = (const char*)g_yb + (size_t)bx * 16384;
#pragma unroll
        for (int i = 0; i < 8; i++) {
            int idx = tid + i * 256;
            int row = idx >> 4;
            int col8 = (idx & 15) << 3;
            cp_async16(sb + OFF_A + tile_off_a(row, col8), xg + row * 256 + col8 * 2);
        }
#pragma unroll
        for (int i = 0; i < 4; i++) {
            int idx = tid + i * 256;
            int row = idx >> 4;
            int col8 = (idx & 15) << 3;
            cp_async16(sb + OFF_B + tile_off_b(row, col8), yg + row * 256 + col8 * 2);
        }
    }
    cp_async_wait_all();
    __syncthreads();

    // ---- mainloop: K=128 in 8 k-steps of 16; warp tile 32x32 ----
    float acc[2][4][4];
#pragma unroll
    for (int mi = 0; mi < 2; mi++)
#pragma unroll
        for (int ni = 0; ni < 4; ni++)
#pragma unroll
            for (int q = 0; q < 4; q++) acc[mi][ni][q] = 0.0f;

    const int a_row = wrow * 32 + (lane & 15);
    const int a_k8 = (lane >> 4) << 3;
    const int b_row = wcol * 32 + ((lane >> 4) << 3) + (lane & 7);
    const int b_k8 = ((lane >> 3) & 1) << 3;

#pragma unroll
    for (int ks = 0; ks < 8; ks++) {
        const int kc = ks * 16;
        uint32_t a[2][4];
#pragma unroll
        for (int mi = 0; mi < 2; mi++)
            ldsm_x4(a[mi][0], a[mi][1], a[mi][2], a[mi][3],
                    sb + OFF_A + tile_off_a(a_row + mi * 16, kc + a_k8));
        uint32_t b[2][4];
#pragma unroll
        for (int nq = 0; nq < 2; nq++)
            ldsm_x4(b[nq][0], b[nq][1], b[nq][2], b[nq][3],
                    sb + OFF_B + tile_off_b(b_row + nq * 16, kc + b_k8));
#pragma unroll
        for (int mi = 0; mi < 2; mi++)
#pragma unroll
            for (int ni = 0; ni < 4; ni++) {
                uint32_t b0 = b[ni >> 1][(ni & 1) * 2];
                uint32_t b1 = b[ni >> 1][(ni & 1) * 2 + 1];
                mma16816(acc[mi][ni][0], acc[mi][ni][1], acc[mi][ni][2], acc[mi][ni][3],
                         a[mi][0], a[mi][1], a[mi][2], a[mi][3], b0, b1);
            }
    }

    // ---- epilogue: packed exp + masked reduce ----
    const unsigned long long C2    = pk2(4.80898346962988f, 4.80898346962988f);
    const unsigned long long MAG2  = pk2(12582912.0f, 12582912.0f);
    const unsigned long long NMAG2 = pk2(-12582912.0f, -12582912.0f);
    const unsigned long long NONE2 = pk2(-1.0f, -1.0f);
    const unsigned long long ONE2  = pk2(1.0f, 1.0f);
    const unsigned long long P5    = pk2(1.3333558146e-3f, 1.3333558146e-3f);
    const unsigned long long P4    = pk2(9.6181291076e-3f, 9.6181291076e-3f);
    const unsigned long long P3    = pk2(5.5504108664e-2f, 5.5504108664e-2f);
    const unsigned long long P2    = pk2(2.4022650696e-1f, 2.4022650696e-1f);
    const unsigned long long P1    = pk2(6.9314718056e-1f, 6.9314718056e-1f);

    unsigned long long sall2 = 0ull;
    float spos = 0.0f;
    // tile covers cols j = bx*64 + c; j%512 == t  <=>  c == t - (bx&7)*64
    const int cb512 = (bx & 7) << 6;
    const int cbase = wcol * 32 + (lane & 3) * 2;
    const int* trk_s = (const int*)(smem + OFF_TRK);

#pragma unroll
    for (int mi = 0; mi < 2; mi++) {
        const int r0 = wrow * 32 + mi * 16 + (lane >> 2);
        const int pc0 = trk_s[r0] - cb512;      // pos col (may be out of [0,64))
        const int pc1 = trk_s[r0 + 8] - cb512;
#pragma unroll
        for (int ni = 0; ni < 4; ni++) {
            const int c = cbase + ni * 8;
#pragma unroll
            for (int h = 0; h < 2; h++) {
                unsigned long long s2 = pk2(acc[mi][ni][2 * h], acc[mi][ni][2 * h + 1]);
                unsigned long long z  = mulx2(s2, C2);
                unsigned long long tt = addx2(z, MAG2);
                unsigned long long nf = addx2(tt, NMAG2);
                unsigned long long f  = fmax2(nf, NONE2, z);
                unsigned long long p  = fmax2(P5, f, P4);
                p = fmax2(p, f, P3);
                p = fmax2(p, f, P2);
                p = fmax2(p, f, P1);
                p = fmax2(p, f, ONE2);
                uint32_t tlo, thi;
                upk2u(tt, tlo, thi);
                uint32_t slo = (tlo + 0xB4C0007Fu) << 23;
                uint32_t shi = (thi + 0xB4C0007Fu) << 23;
                unsigned long long e2 = mulx2(p, pk2u(slo, shi));
                sall2 = addx2(sall2, e2);
                const int pc = h ? pc1 : pc0;
                if ((pc | 1) == (c | 1)) {
                    float e0, e1;
                    upk2(e2, e0, e1);
                    spos += (pc == c) ? e0 : e1;
                }
            }
        }
    }

    // CTA reduce + partial write
    float a0, a1;
    upk2(sall2, a0, a1);
    float sall = a0 + a1;
#pragma unroll
    for (int o = 16; o > 0; o >>= 1) {
        sall += __shfl_down_sync(0xffffffffu, sall, o);
        spos += __shfl_down_sync(0xffffffffu, spos, o);
    }
    float* red = (float*)(smem + OFF_RED);
    if (lane == 0) { red[wid] = sall; red[wid + 8] = spos; }
    __syncthreads();

    int* flag = (int*)(smem + OFF_FLAG);
    if (tid == 0) {
        float a = 0.0f, p = 0.0f;
#pragma unroll
        for (int w = 0; w < 8; w++) { a += red[w]; p += red[w + 8]; }
        g_partials[by * NTILE_C + bx] = make_float2(p, a);
        __threadfence();
        int old = atomicAdd(&g_ctr, 1);
        *flag = (old == NPART - 1) ? 1 : 0;
    }
    __syncthreads();

    // Last CTA finalizes (deterministic fixed-order reduction).
    if (*flag) {
        __threadfence();
        double a = 0.0, p = 0.0;
        for (int i = tid; i < NPART; i += 256) {
            float2 v = g_partials[i];
            p += (double)v.x;
            a += (double)v.y;
        }
#pragma unroll
        for (int o = 16; o > 0; o >>= 1) {
            a += __shfl_down_sync(0xffffffffu, a, o);
            p += __shfl_down_sync(0xffffffffu, p, o);
        }
        double* dred = (double*)(smem + OFF_DRED);
        if (lane == 0) { dred[wid] = a; dred[wid + 8] = p; }
        __syncthreads();
        if (tid == 0) {
            double aa = 0.0, pp = 0.0;
#pragma unroll
            for (int w = 0; w < 8; w++) { aa += dred[w]; pp += dred[w + 8]; }
            double den = aa - pp;
            double r = pp / (den + 1e-9) + 1e-10;
            out[0] = (float)(-log(r));
            g_ctr = 0;  // reset for next graph replay
        }
    }
}

extern "C" void kernel_launch(void* const* d_in, const int* in_sizes, int n_in,
                              void* d_out, int out_size) {
    const float* x = (const float*)d_in[0];    // [32768,128]
    const int* trk = (const int*)d_in[1];      // [32768]
    const float* y = (const float*)d_in[2];    // [512,8,128]

    cudaFuncSetAttribute(cl_mma_kernel, cudaFuncAttributeMaxDynamicSharedMemorySize,
                         SMEM_TOTAL);

    const int xn4 = NROWS * 128 / 4;
    const int yn4 = NCOLS * 128 / 4;
    cvt_bf16_all<<<(xn4 + yn4 + 255) / 256, 256>>>(x, y);

    dim3 grid(NTILE_C, NTILE_R);   // (64, 256)
    cl_mma_kernel<<<grid, 256, SMEM_TOTAL>>>(trk, (float*)d_out);
}

// round 11
// speedup vs baseline: 1.0089x; 1.0089x over previous
#include <cuda_runtime.h>
#include <cuda_bf16.h>
#include <cstdint>

// ContrastiveLoss: loss = -log(num/(den+1e-9)+1e-10)
//   S[i,j] = exp((x[i] . y_sel[j]) / 0.3),  y_sel = y.reshape(4096,128)
//   pos(i,j) = (track_idxs[i] == (j % 512))
// x [32768,128] f32, track_idxs [32768] i32, y [512,8,128] f32, out [1] f32.
//
// bf16 mma.sync.m16n8k16; CTA tile 128x64 (warp tile 32x32, 8 warps),
// 3 CTAs/SM (24 warps) for latency hiding, fused packed-f32x2 exp + masked
// reduce, last-CTA finalize.

#define NROWS 32768
#define NCOLS 4096
#define NTILE_R (NROWS / 128)   /* 256 */
#define NTILE_C (NCOLS / 64)    /* 64  */
#define NPART (NTILE_R * NTILE_C) /* 16384 */

__device__ __nv_bfloat16 g_xb[NROWS * 128];
__device__ __nv_bfloat16 g_yb[NCOLS * 128];
__device__ float2 g_partials[NPART];
__device__ int g_ctr = 0;

// ---------------- helpers ----------------
__device__ __forceinline__ uint32_t smem_to_u32(const void* p) {
    uint32_t a;
    asm("{ .reg .u64 t; cvta.to.shared.u64 t, %1; cvt.u32.u64 %0, t; }"
        : "=r"(a) : "l"(p));
    return a;
}

__device__ __forceinline__ void cp_async16(uint32_t saddr, const void* gaddr) {
    asm volatile("cp.async.cg.shared.global [%0], [%1], 16;"
                 :: "r"(saddr), "l"(gaddr) : "memory");
}
__device__ __forceinline__ void cp_async_wait_all() {
    asm volatile("cp.async.commit_group;\n\tcp.async.wait_group 0;" ::: "memory");
}

__device__ __forceinline__ void ldsm_x4(uint32_t& r0, uint32_t& r1, uint32_t& r2,
                                        uint32_t& r3, uint32_t addr) {
    asm volatile("ldmatrix.sync.aligned.m8n8.x4.shared.b16 {%0,%1,%2,%3}, [%4];"
                 : "=r"(r0), "=r"(r1), "=r"(r2), "=r"(r3) : "r"(addr));
}

__device__ __forceinline__ void mma16816(float& d0, float& d1, float& d2, float& d3,
                                         uint32_t a0, uint32_t a1, uint32_t a2,
                                         uint32_t a3, uint32_t b0, uint32_t b1) {
    asm volatile(
        "mma.sync.aligned.m16n8k16.row.col.f32.bf16.bf16.f32 "
        "{%0,%1,%2,%3}, {%4,%5,%6,%7}, {%8,%9}, {%0,%1,%2,%3};"
        : "+f"(d0), "+f"(d1), "+f"(d2), "+f"(d3)
        : "r"(a0), "r"(a1), "r"(a2), "r"(a3), "r"(b0), "r"(b1));
}

// packed f32x2 ops
__device__ __forceinline__ unsigned long long pk2(float lo, float hi) {
    unsigned long long r;
    asm("mov.b64 %0, {%1, %2};" : "=l"(r) : "f"(lo), "f"(hi));
    return r;
}
__device__ __forceinline__ void upk2(unsigned long long v, float& lo, float& hi) {
    asm("mov.b64 {%0, %1}, %2;" : "=f"(lo), "=f"(hi) : "l"(v));
}
__device__ __forceinline__ void upk2u(unsigned long long v, uint32_t& lo, uint32_t& hi) {
    asm("mov.b64 {%0, %1}, %2;" : "=r"(lo), "=r"(hi) : "l"(v));
}
__device__ __forceinline__ unsigned long long pk2u(uint32_t lo, uint32_t hi) {
    unsigned long long r;
    asm("mov.b64 %0, {%1, %2};" : "=l"(r) : "r"(lo), "r"(hi));
    return r;
}
__device__ __forceinline__ unsigned long long addx2(unsigned long long a, unsigned long long b) {
    unsigned long long d;
    asm("add.rn.f32x2 %0, %1, %2;" : "=l"(d) : "l"(a), "l"(b));
    return d;
}
__device__ __forceinline__ unsigned long long mulx2(unsigned long long a, unsigned long long b) {
    unsigned long long d;
    asm("mul.rn.f32x2 %0, %1, %2;" : "=l"(d) : "l"(a), "l"(b));
    return d;
}
__device__ __forceinline__ unsigned long long fmax2(unsigned long long a, unsigned long long b,
                                                    unsigned long long c) {
    unsigned long long d;
    asm("fma.rn.f32x2 %0, %1, %2, %3;" : "=l"(d) : "l"(a), "l"(b), "l"(c));
    return d;
}

// blocked-atom K-major SW128 layouts.
// A tile: 128 rows x 128 bf16 -> 16 atom-rows x 2 atom-cols (32KB).
__device__ __forceinline__ uint32_t tile_off_a(int row, int col8) {
    uint32_t atom = (uint32_t)((row >> 3) + ((col8 >> 6) << 4));
    uint32_t boff = atom * 1024u + (uint32_t)(row & 7) * 128u + (uint32_t)(col8 & 63) * 2u;
    return boff ^ ((boff >> 3) & 0x70u);
}
// B tile: 64 rows x 128 bf16 -> 8 atom-rows x 2 atom-cols (16KB).
__device__ __forceinline__ uint32_t tile_off_b(int row, int col8) {
    uint32_t atom = (uint32_t)((row >> 3) + ((col8 >> 6) << 3));
    uint32_t boff = atom * 1024u + (uint32_t)(row & 7) * 128u + (uint32_t)(col8 & 63) * 2u;
    return boff ^ ((boff >> 3) & 0x70u);
}

#define OFF_TRK  0       /* 128 ints */
#define OFF_RED  512     /* 16 floats */
#define OFF_DRED 576     /* 16 doubles */
#define OFF_FLAG 704     /* int */
#define OFF_A    1024    /* 32KB */
#define OFF_B    33792   /* 16KB */
#define SMEM_TOTAL 50176

// ---------------- kernels ----------------
__global__ __launch_bounds__(256)
void cvt_bf16_all(const float* __restrict__ x, const float* __restrict__ y) {
    const int xn4 = NROWS * 128 / 4;
    const int yn4 = NCOLS * 128 / 4;
    int i = blockIdx.x * blockDim.x + threadIdx.x;
    const float4* src;
    uint2* dst;
    int idx;
    if (i < xn4) {
        src = (const float4*)x; dst = (uint2*)g_xb; idx = i;
    } else if (i < xn4 + yn4) {
        src = (const float4*)y; dst = (uint2*)g_yb; idx = i - xn4;
    } else return;
    float4 v = src[idx];
    __nv_bfloat162 a = __floats2bfloat162_rn(v.x, v.y);
    __nv_bfloat162 b = __floats2bfloat162_rn(v.z, v.w);
    uint2 o;
    o.x = *(uint32_t*)&a;
    o.y = *(uint32_t*)&b;
    dst[idx] = o;
}

__global__ __launch_bounds__(256, 3)
void cl_mma_kernel(const int* __restrict__ trk, float* __restrict__ out) {
    extern __shared__ char smem[];
    const uint32_t sb = smem_to_u32(smem);
    const int tid = threadIdx.x;
    const int wid = tid >> 5, lane = tid & 31;
    const int bx = blockIdx.x;   // col tile 0..63 (64 cols each)
    const int by = blockIdx.y;   // row tile 0..255

    const int wrow = wid & 3;    // 4 row groups x 32 rows
    const int wcol = wid >> 2;   // 2 col groups x 32 cols

    if (tid < 128) ((int*)(smem + OFF_TRK))[tid] = trk[by * 128 + tid];

    // Stage A (128x128 bf16 = 2048 x 16B) and B (64x128 bf16 = 1024 x 16B).
    {
        const char* xg = (const char*)g_xb + (size_t)by * 32768;
        const char* yg = (const char*)g_yb + (size_t)bx * 16384;
#pragma unroll
        for (int i = 0; i < 8; i++) {
            int idx = tid + i * 256;
            int row = idx >> 4;
            int col8 = (idx & 15) << 3;
            cp_async16(sb + OFF_A + tile_off_a(row, col8), xg + row * 256 + col8 * 2);
        }
#pragma unroll
        for (int i = 0; i < 4; i++) {
            int idx = tid + i * 256;
            int row = idx >> 4;
            int col8 = (idx & 15) << 3;
            cp_async16(sb + OFF_B + tile_off_b(row, col8), yg + row * 256 + col8 * 2);
        }
    }
    cp_async_wait_all();
    __syncthreads();

    // ---- mainloop: K=128 in 8 k-steps of 16; warp tile 32x32 ----
    float acc[2][4][4];
#pragma unroll
    for (int mi = 0; mi < 2; mi++)
#pragma unroll
        for (int ni = 0; ni < 4; ni++)
#pragma unroll
            for (int q = 0; q < 4; q++) acc[mi][ni][q] = 0.0f;

    const int a_row = wrow * 32 + (lane & 15);
    const int a_k8 = (lane >> 4) << 3;
    const int b_row = wcol * 32 + ((lane >> 4) << 3) + (lane & 7);
    const int b_k8 = ((lane >> 3) & 1) << 3;

#pragma unroll
    for (int ks = 0; ks < 8; ks++) {
        const int kc = ks * 16;
        uint32_t a[2][4];
#pragma unroll
        for (int mi = 0; mi < 2; mi++)
            ldsm_x4(a[mi][0], a[mi][1], a[mi][2], a[mi][3],
                    sb + OFF_A + tile_off_a(a_row + mi * 16, kc + a_k8));
        uint32_t b[2][4];
#pragma unroll
        for (int nq = 0; nq < 2; nq++)
            ldsm_x4(b[nq][0], b[nq][1], b[nq][2], b[nq][3],
                    sb + OFF_B + tile_off_b(b_row + nq * 16, kc + b_k8));
#pragma unroll
        for (int mi = 0; mi < 2; mi++)
#pragma unroll
            for (int ni = 0; ni < 4; ni++) {
                uint32_t b0 = b[ni >> 1][(ni & 1) * 2];
                uint32_t b1 = b[ni >> 1][(ni & 1) * 2 + 1];
                mma16816(acc[mi][ni][0], acc[mi][ni][1], acc[mi][ni][2], acc[mi][ni][3],
                         a[mi][0], a[mi][1], a[mi][2], a[mi][3], b0, b1);
            }
    }

    // ---- epilogue: packed exp + masked reduce ----
    const unsigned long long C2    = pk2(4.80898346962988f, 4.80898346962988f);
    const unsigned long long MAG2  = pk2(12582912.0f, 12582912.0f);
    const unsigned long long NMAG2 = pk2(-12582912.0f, -12582912.0f);
    const unsigned long long NONE2 = pk2(-1.0f, -1.0f);
    const unsigned long long ONE2  = pk2(1.0f, 1.0f);
    const unsigned long long P5    = pk2(1.3333558146e-3f, 1.3333558146e-3f);
    const unsigned long long P4    = pk2(9.6181291076e-3f, 9.6181291076e-3f);
    const unsigned long long P3    = pk2(5.5504108664e-2f, 5.5504108664e-2f);
    const unsigned long long P2    = pk2(2.4022650696e-1f, 2.4022650696e-1f);
    const unsigned long long P1    = pk2(6.9314718056e-1f, 6.9314718056e-1f);

    unsigned long long sall2 = 0ull;
    float spos = 0.0f;
    // tile covers cols j = bx*64 + c; j%512 == t  <=>  c == t - (bx&7)*64
    const int cb512 = (bx & 7) << 6;
    const int cbase = wcol * 32 + (lane & 3) * 2;
    const int* trk_s = (const int*)(smem + OFF_TRK);

#pragma unroll
    for (int mi = 0; mi < 2; mi++) {
        const int r0 = wrow * 32 + mi * 16 + (lane >> 2);
        const int pc0 = trk_s[r0] - cb512;      // pos col (may be out of [0,64))
        const int pc1 = trk_s[r0 + 8] - cb512;
#pragma unroll
        for (int ni = 0; ni < 4; ni++) {
            const int c = cbase + ni * 8;
#pragma unroll
            for (int h = 0; h < 2; h++) {
                unsigned long long s2 = pk2(acc[mi][ni][2 * h], acc[mi][ni][2 * h + 1]);
                unsigned long long z  = mulx2(s2, C2);
                unsigned long long tt = addx2(z, MAG2);
                unsigned long long nf = addx2(tt, NMAG2);
                unsigned long long f  = fmax2(nf, NONE2, z);
                unsigned long long p  = fmax2(P5, f, P4);
                p = fmax2(p, f, P3);
                p = fmax2(p, f, P2);
                p = fmax2(p, f, P1);
                p = fmax2(p, f, ONE2);
                uint32_t tlo, thi;
                upk2u(tt, tlo, thi);
                uint32_t slo = (tlo + 0xB4C0007Fu) << 23;
                uint32_t shi = (thi + 0xB4C0007Fu) << 23;
                unsigned long long e2 = mulx2(p, pk2u(slo, shi));
                sall2 = addx2(sall2, e2);
                const int pc = h ? pc1 : pc0;
                if ((pc | 1) == (c | 1)) {
                    float e0, e1;
                    upk2(e2, e0, e1);
                    spos += (pc == c) ? e0 : e1;
                }
            }
        }
    }

    // CTA reduce + partial write
    float a0, a1;
    upk2(sall2, a0, a1);
    float sall = a0 + a1;
#pragma unroll
    for (int o = 16; o > 0; o >>= 1) {
        sall += __shfl_down_sync(0xffffffffu, sall, o);
        spos += __shfl_down_sync(0xffffffffu, spos, o);
    }
    float* red = (float*)(smem + OFF_RED);
    if (lane == 0) { red[wid] = sall; red[wid + 8] = spos; }
    __syncthreads();

    int* flag = (int*)(smem + OFF_FLAG);
    if (tid == 0) {
        float a = 0.0f, p = 0.0f;
#pragma unroll
        for (int w = 0; w < 8; w++) { a += red[w]; p += red[w + 8]; }
        g_partials[by * NTILE_C + bx] = make_float2(p, a);
        __threadfence();
        int old = atomicAdd(&g_ctr, 1);
        *flag = (old == NPART - 1) ? 1 : 0;
    }
    __syncthreads();

    // Last CTA finalizes (deterministic fixed-order reduction).
    if (*flag) {
        __threadfence();
        double a = 0.0, p = 0.0;
        for (int i = tid; i < NPART; i += 256) {
            float2 v = g_partials[i];
            p += (double)v.x;
            a += (double)v.y;
        }
#pragma unroll
        for (int o = 16; o > 0; o >>= 1) {
            a += __shfl_down_sync(0xffffffffu, a, o);
            p += __shfl_down_sync(0xffffffffu, p, o);
        }
        double* dred = (double*)(smem + OFF_DRED);
        if (lane == 0) { dred[wid] = a; dred[wid + 8] = p; }
        __syncthreads();
        if (tid == 0) {
            double aa = 0.0, pp = 0.0;
#pragma unroll
            for (int w = 0; w < 8; w++) { aa += dred[w]; pp += dred[w + 8]; }
            double den = aa - pp;
            double r = pp / (den + 1e-9) + 1e-10;
            out[0] = (float)(-log(r));
            g_ctr = 0;  // reset for next graph replay
        }
    }
}

extern "C" void kernel_launch(void* const* d_in, const int* in_sizes, int n_in,
                              void* d_out, int out_size) {
    const float* x = (const float*)d_in[0];    // [32768,128]
    const int* trk = (const int*)d_in[1];      // [32768]
    const float* y = (const float*)d_in[2];    // [512,8,128]

    cudaFuncSetAttribute(cl_mma_kernel, cudaFuncAttributeMaxDynamicSharedMemorySize,
                         SMEM_TOTAL);

    const int xn4 = NROWS * 128 / 4;
    const int yn4 = NCOLS * 128 / 4;
    cvt_bf16_all<<<(xn4 + yn4 + 255) / 256, 256>>>(x, y);

    dim3 grid(NTILE_C, NTILE_R);   // (64, 256)
    cl_mma_kernel<<<grid, 256, SMEM_TOTAL>>>(trk, (float*)d_out);
}

// round 12
// speedup vs baseline: 1.1852x; 1.1747x over previous
#include <cuda_runtime.h>
#include <cuda_bf16.h>
#include <cstdint>

// ContrastiveLoss: loss = -log(num/(den+1e-9)+1e-10)
//   S[i,j] = exp((x[i] . y_sel[j]) / 0.3),  y_sel = y.reshape(4096,128)
//   pos(i,j) = (track_idxs[i] == (j % 512))
// x [32768,128] f32, track_idxs [32768] i32, y [512,8,128] f32, out [1] f32.
//
// bf16 mma.sync.m16n8k16, CTA tile 128x128 (warp tile 32x64, 8 warps, natural
// regs), K split into two 64-wide double-buffered halves, x pre-scaled by
// log2(e)/0.3 so the accumulator is the exp2 argument, deg-4 poly exp on the
// packed f32x2 pipe, masked reduce, last-CTA finalize.

#define NROWS 32768
#define NCOLS 4096
#define NTILE_R (NROWS / 128)   /* 256 */
#define NTILE_C (NCOLS / 128)   /* 32  */
#define NPART (NTILE_R * NTILE_C) /* 8192 */

__device__ __nv_bfloat16 g_xb[NROWS * 128];
__device__ __nv_bfloat16 g_yb[NCOLS * 128];
__device__ float2 g_partials[NPART];
__device__ int g_ctr = 0;

// ---------------- helpers ----------------
__device__ __forceinline__ uint32_t smem_to_u32(const void* p) {
    uint32_t a;
    asm("{ .reg .u64 t; cvta.to.shared.u64 t, %1; cvt.u32.u64 %0, t; }"
        : "=r"(a) : "l"(p));
    return a;
}

__device__ __forceinline__ void cp_async16(uint32_t saddr, const void* gaddr) {
    asm volatile("cp.async.cg.shared.global [%0], [%1], 16;"
                 :: "r"(saddr), "l"(gaddr) : "memory");
}

__device__ __forceinline__ void ldsm_x4(uint32_t& r0, uint32_t& r1, uint32_t& r2,
                                        uint32_t& r3, uint32_t addr) {
    asm volatile("ldmatrix.sync.aligned.m8n8.x4.shared.b16 {%0,%1,%2,%3}, [%4];"
                 : "=r"(r0), "=r"(r1), "=r"(r2), "=r"(r3) : "r"(addr));
}

__device__ __forceinline__ void mma16816(float& d0, float& d1, float& d2, float& d3,
                                         uint32_t a0, uint32_t a1, uint32_t a2,
                                         uint32_t a3, uint32_t b0, uint32_t b1) {
    asm volatile(
        "mma.sync.aligned.m16n8k16.row.col.f32.bf16.bf16.f32 "
        "{%0,%1,%2,%3}, {%4,%5,%6,%7}, {%8,%9}, {%0,%1,%2,%3};"
        : "+f"(d0), "+f"(d1), "+f"(d2), "+f"(d3)
        : "r"(a0), "r"(a1), "r"(a2), "r"(a3), "r"(b0), "r"(b1));
}

// packed f32x2 ops
__device__ __forceinline__ unsigned long long pk2(float lo, float hi) {
    unsigned long long r;
    asm("mov.b64 %0, {%1, %2};" : "=l"(r) : "f"(lo), "f"(hi));
    return r;
}
__device__ __forceinline__ void upk2(unsigned long long v, float& lo, float& hi) {
    asm("mov.b64 {%0, %1}, %2;" : "=f"(lo), "=f"(hi) : "l"(v));
}
__device__ __forceinline__ void upk2u(unsigned long long v, uint32_t& lo, uint32_t& hi) {
    asm("mov.b64 {%0, %1}, %2;" : "=r"(lo), "=r"(hi) : "l"(v));
}
__device__ __forceinline__ unsigned long long pk2u(uint32_t lo, uint32_t hi) {
    unsigned long long r;
    asm("mov.b64 %0, {%1, %2};" : "=l"(r) : "r"(lo), "r"(hi));
    return r;
}
__device__ __forceinline__ unsigned long long addx2(unsigned long long a, unsigned long long b) {
    unsigned long long d;
    asm("add.rn.f32x2 %0, %1, %2;" : "=l"(d) : "l"(a), "l"(b));
    return d;
}
__device__ __forceinline__ unsigned long long mulx2(unsigned long long a, unsigned long long b) {
    unsigned long long d;
    asm("mul.rn.f32x2 %0, %1, %2;" : "=l"(d) : "l"(a), "l"(b));
    return d;
}
__device__ __forceinline__ unsigned long long fmax2(unsigned long long a, unsigned long long b,
                                                    unsigned long long c) {
    unsigned long long d;
    asm("fma.rn.f32x2 %0, %1, %2, %3;" : "=l"(d) : "l"(a), "l"(b), "l"(c));
    return d;
}

// K-half tile: 128 rows x 64 bf16 (128B/row = one SW128 atom row).
// Atom = 8 rows x 128B; 16 atoms; conflict-free for ldmatrix + 16B stores.
__device__ __forceinline__ uint32_t tile_off64(int row, int col8) {
    uint32_t boff = (uint32_t)(row >> 3) * 1024u + (uint32_t)(row & 7) * 128u +
                    (uint32_t)col8 * 2u;
    return boff ^ ((boff >> 3) & 0x70u);
}

#define OFF_TRK  0       /* 128 ints */
#define OFF_RED  512     /* 16 floats */
#define OFF_DRED 576     /* 16 doubles */
#define OFF_FLAG 704     /* int */
#define OFF_A0   1024            /* 16KB */
#define OFF_B0   (OFF_A0+16384)  /* 16KB */
#define OFF_A1   (OFF_B0+16384)  /* 16KB */
#define OFF_B1   (OFF_A1+16384)  /* 16KB */
#define SMEM_TOTAL (OFF_B1+16384)

// ---------------- kernels ----------------
__global__ __launch_bounds__(256)
void cvt_bf16_all(const float* __restrict__ x, const float* __restrict__ y) {
    const int xn4 = NROWS * 128 / 4;
    const int yn4 = NCOLS * 128 / 4;
    int i = blockIdx.x * blockDim.x + threadIdx.x;
    if (i < xn4) {
        // pre-scale x by log2(e)/0.3 so GEMM accumulator is the exp2 argument
        const float C = 4.80898346962988f;
        float4 v = ((const float4*)x)[i];
        __nv_bfloat162 a = __floats2bfloat162_rn(v.x * C, v.y * C);
        __nv_bfloat162 b = __floats2bfloat162_rn(v.z * C, v.w * C);
        uint2 o;
        o.x = *(uint32_t*)&a;
        o.y = *(uint32_t*)&b;
        ((uint2*)g_xb)[i] = o;
    } else if (i < xn4 + yn4) {
        int idx = i - xn4;
        float4 v = ((const float4*)y)[idx];
        __nv_bfloat162 a = __floats2bfloat162_rn(v.x, v.y);
        __nv_bfloat162 b = __floats2bfloat162_rn(v.z, v.w);
        uint2 o;
        o.x = *(uint32_t*)&a;
        o.y = *(uint32_t*)&b;
        ((uint2*)g_yb)[idx] = o;
    }
}

__global__ __launch_bounds__(256)
void cl_mma_kernel(const int* __restrict__ trk, float* __restrict__ out) {
    extern __shared__ char smem[];
    const uint32_t sb = smem_to_u32(smem);
    const int tid = threadIdx.x;
    const int wid = tid >> 5, lane = tid & 31;
    const int bx = blockIdx.x;   // col tile 0..31
    const int by = blockIdx.y;   // row tile 0..255

    const int wrow = wid & 3;    // 4 row groups x 32 rows
    const int wcol = wid >> 2;   // 2 col groups x 64 cols

    if (tid < 128) ((int*)(smem + OFF_TRK))[tid] = trk[by * 128 + tid];

    // Stage both K-halves: (A0,B0) group 0, (A1,B1) group 1. Rows are 256B in
    // gmem; half h covers bytes [h*128, h*128+128).
    {
        const char* xg = (const char*)g_xb + (size_t)by * 32768;
        const char* yg = (const char*)g_yb + (size_t)bx * 32768;
#pragma unroll
        for (int i = 0; i < 4; i++) {
            int idx = tid + i * 256;      // 0..1023
            int row = idx >> 3;
            int q16 = (idx & 7) << 4;     // byte offset within 128B half-row
            uint32_t so = tile_off64(row, q16 >> 1);
            cp_async16(sb + OFF_A0 + so, xg + row * 256 + q16);
            cp_async16(sb + OFF_B0 + so, yg + row * 256 + q16);
        }
        asm volatile("cp.async.commit_group;" ::: "memory");
#pragma unroll
        for (int i = 0; i < 4; i++) {
            int idx = tid + i * 256;
            int row = idx >> 3;
            int q16 = (idx & 7) << 4;
            uint32_t so = tile_off64(row, q16 >> 1);
            cp_async16(sb + OFF_A1 + so, xg + row * 256 + 128 + q16);
            cp_async16(sb + OFF_B1 + so, yg + row * 256 + 128 + q16);
        }
        asm volatile("cp.async.commit_group;" ::: "memory");
    }

    float acc[2][8][4];
#pragma unroll
    for (int mi = 0; mi < 2; mi++)
#pragma unroll
        for (int ni = 0; ni < 8; ni++)
#pragma unroll
            for (int q = 0; q < 4; q++) acc[mi][ni][q] = 0.0f;

    const int a_row = wrow * 32 + (lane & 15);
    const int a_k8 = (lane >> 4) << 3;
    const int b_row = wcol * 64 + ((lane >> 4) << 3) + (lane & 7);
    const int b_k8 = ((lane >> 3) & 1) << 3;

    asm volatile("cp.async.wait_group 1;" ::: "memory");
    __syncthreads();

#pragma unroll
    for (int half = 0; half < 2; half++) {
        const uint32_t offA = half ? OFF_A1 : OFF_B0 - 16384;  // OFF_A0
        const uint32_t offB = half ? OFF_B1 : OFF_B0;
#pragma unroll
        for (int ks = 0; ks < 4; ks++) {
            const int kc = ks * 16;
            uint32_t a[2][4];
#pragma unroll
            for (int mi = 0; mi < 2; mi++)
                ldsm_x4(a[mi][0], a[mi][1], a[mi][2], a[mi][3],
                        sb + offA + tile_off64(a_row + mi * 16, kc + a_k8));
            uint32_t b[4][4];
#pragma unroll
            for (int nq = 0; nq < 4; nq++)
                ldsm_x4(b[nq][0], b[nq][1], b[nq][2], b[nq][3],
                        sb + offB + tile_off64(b_row + nq * 16, kc + b_k8));
#pragma unroll
            for (int mi = 0; mi < 2; mi++)
#pragma unroll
                for (int ni = 0; ni < 8; ni++) {
                    uint32_t b0 = b[ni >> 1][(ni & 1) * 2];
                    uint32_t b1 = b[ni >> 1][(ni & 1) * 2 + 1];
                    mma16816(acc[mi][ni][0], acc[mi][ni][1], acc[mi][ni][2],
                             acc[mi][ni][3], a[mi][0], a[mi][1], a[mi][2],
                             a[mi][3], b0, b1);
                }
        }
        if (half == 0) {
            asm volatile("cp.async.wait_group 0;" ::: "memory");
            __syncthreads();
        }
    }

    // ---- epilogue: acc is already z = s*log2(e)/0.3; exp2 via deg-4 poly ----
    const unsigned long long MAG2  = pk2(12582912.0f, 12582912.0f);
    const unsigned long long NMAG2 = pk2(-12582912.0f, -12582912.0f);
    const unsigned long long NONE2 = pk2(-1.0f, -1.0f);
    const unsigned long long ONE2  = pk2(1.0f, 1.0f);
    const unsigned long long P4    = pk2(9.6181291076e-3f, 9.6181291076e-3f);
    const unsigned long long P3    = pk2(5.5504108664e-2f, 5.5504108664e-2f);
    const unsigned long long P2    = pk2(2.4022650696e-1f, 2.4022650696e-1f);
    const unsigned long long P1    = pk2(6.9314718056e-1f, 6.9314718056e-1f);

    unsigned long long sall2 = 0ull;
    float spos = 0.0f;
    const int bxm = bx & 3;
    const int cbase = wcol * 64 + (lane & 3) * 2;
    const int* trk_s = (const int*)(smem + OFF_TRK);

#pragma unroll
    for (int mi = 0; mi < 2; mi++) {
        const int r0 = wrow * 32 + mi * 16 + (lane >> 2);
        const int t0 = trk_s[r0];
        const int t1 = trk_s[r0 + 8];
        const int pc0 = ((t0 >> 7) == bxm) ? (t0 & 127) : -1;
        const int pc1 = ((t1 >> 7) == bxm) ? (t1 & 127) : -1;
#pragma unroll
        for (int ni = 0; ni < 8; ni++) {
            const int c = cbase + ni * 8;
#pragma unroll
            for (int h = 0; h < 2; h++) {
                unsigned long long z  = pk2(acc[mi][ni][2 * h], acc[mi][ni][2 * h + 1]);
                unsigned long long tt = addx2(z, MAG2);
                unsigned long long nf = addx2(tt, NMAG2);
                unsigned long long f  = fmax2(nf, NONE2, z);     // f = z - round(z)
                unsigned long long p  = fmax2(P4, f, P3);
                p = fmax2(p, f, P2);
                p = fmax2(p, f, P1);
                p = fmax2(p, f, ONE2);
                uint32_t tlo, thi;
                upk2u(tt, tlo, thi);
                uint32_t slo = (tlo + 0xB4C0007Fu) << 23;
                uint32_t shi = (thi + 0xB4C0007Fu) << 23;
                unsigned long long e2 = mulx2(p, pk2u(slo, shi));
                sall2 = addx2(sall2, e2);
                const int pc = h ? pc1 : pc0;
                if (pc >= 0 && ((pc | 1) == (c | 1))) {
                    float e0, e1;
                    upk2(e2, e0, e1);
                    spos += (pc == c) ? e0 : e1;
                }
            }
        }
    }

    // CTA reduce + partial write
    float a0, a1;
    upk2(sall2, a0, a1);
    float sall = a0 + a1;
#pragma unroll
    for (int o = 16; o > 0; o >>= 1) {
        sall += __shfl_down_sync(0xffffffffu, sall, o);
        spos += __shfl_down_sync(0xffffffffu, spos, o);
    }
    float* red = (float*)(smem + OFF_RED);
    if (lane == 0) { red[wid] = sall; red[wid + 8] = spos; }
    __syncthreads();

    int* flag = (int*)(smem + OFF_FLAG);
    if (tid == 0) {
        float a = 0.0f, p = 0.0f;
#pragma unroll
        for (int w = 0; w < 8; w++) { a += red[w]; p += red[w + 8]; }
        g_partials[by * NTILE_C + bx] = make_float2(p, a);
        __threadfence();
        int old = atomicAdd(&g_ctr, 1);
        *flag = (old == NPART - 1) ? 1 : 0;
    }
    __syncthreads();

    // Last CTA finalizes (deterministic fixed-order reduction).
    if (*flag) {
        __threadfence();
        double a = 0.0, p = 0.0;
        for (int i = tid; i < NPART; i += 256) {
            float2 v = g_partials[i];
            p += (double)v.x;
            a += (double)v.y;
        }
#pragma unroll
        for (int o = 16; o > 0; o >>= 1) {
            a += __shfl_down_sync(0xffffffffu, a, o);
            p += __shfl_down_sync(0xffffffffu, p, o);
        }
        double* dred = (double*)(smem + OFF_DRED);
        if (lane == 0) { dred[wid] = a; dred[wid + 8] = p; }
        __syncthreads();
        if (tid == 0) {
            double aa = 0.0, pp = 0.0;
#pragma unroll
            for (int w = 0; w < 8; w++) { aa += dred[w]; pp += dred[w + 8]; }
            double den = aa - pp;
            double r = pp / (den + 1e-9) + 1e-10;
            out[0] = (float)(-log(r));
            g_ctr = 0;  // reset for next graph replay
        }
    }
}

extern "C" void kernel_launch(void* const* d_in, const int* in_sizes, int n_in,
                              void* d_out, int out_size) {
    const float* x = (const float*)d_in[0];    // [32768,128]
    const int* trk = (const int*)d_in[1];      // [32768]
    const float* y = (const float*)d_in[2];    // [512,8,128]

    cudaFuncSetAttribute(cl_mma_kernel, cudaFuncAttributeMaxDynamicSharedMemorySize,
                         SMEM_TOTAL);

    const int xn4 = NROWS * 128 / 4;
    const int yn4 = NCOLS * 128 / 4;
    cvt_bf16_all<<<(xn4 + yn4 + 255) / 256, 256>>>(x, y);

    dim3 grid(NTILE_C, NTILE_R);   // (32, 256)
    cl_mma_kernel<<<grid, 256, SMEM_TOTAL>>>(trk, (float*)d_out);
}